// round 16
// baseline (speedup 1.0000x reference)
#include <cuda_runtime.h>
#include <math.h>

#define BH     32
#define LSEQ   4096
#define DIM    64
#define NS     41        // sample_k == n_top == 41
#define NSPLIT 16
#define CHUNK  (LSEQ / NSPLIT)   // 256
#define KTILE  128
#define QROWS  44                // padded q rows in kD (rows >= 41 are zero)
#define BHHALF (BH / 2)

// ---------------- device scratch (no allocations allowed) ----------------
__device__ float g_m[BH * LSEQ];                    // 512 KB
__device__ int   g_topq[BH * NS];
__device__ float g_vmean[BH * DIM];
__device__ float g_vpart[BH * 16 * DIM];
__device__ float g_pacc[BH * NSPLIT * NS * DIM];    // ~5.4 MB
__device__ float g_pm[BH * NSPLIT * NS];
__device__ float g_pl[BH * NSPLIT * NS];

// ---------------- Kernel A: m = max_s(q.k_s) - mean_s(q.k_s) ----------------
// kI fused: dtype of index_sample auto-detected in-kernel, body templated.
// 8 lanes per query; contiguous lane mapping: each warp-LDG covers full 128B
// lines (2 wavefronts per (query,key) pair = floor). Keys in chunks of 4 (MLP).
// qid0 selects the bh-half (pipeline with kB).
template<typename IdxT>
__device__ __forceinline__ void kA_impl(const float* __restrict__ q,
                                        const float* __restrict__ k,
                                        const IdxT* __restrict__ idx,
                                        int bh, int qq, int qid, int sub) {
    const float4* qr = (const float4*)(q + ((size_t)bh * LSEQ + qq) * DIM);
    float4 qa = qr[sub];          // dims [4*sub, 4*sub+4)
    float4 qb = qr[sub + 8];      // dims [32+4*sub, 32+4*sub+4)
    const float* kb = k + (size_t)bh * LSEQ * DIM;
    const IdxT* ip = idx + (size_t)qq * NS;

    float mx = -INFINITY, sm = 0.f;
#pragma unroll
    for (int u = 0; u < 10; u++) {
        int id0 = (int)ip[u * 4 + 0];
        int id1 = (int)ip[u * 4 + 1];
        int id2 = (int)ip[u * 4 + 2];
        int id3 = (int)ip[u * 4 + 3];
        const float4* k0 = (const float4*)(kb + (size_t)id0 * DIM);
        const float4* k1 = (const float4*)(kb + (size_t)id1 * DIM);
        const float4* k2 = (const float4*)(kb + (size_t)id2 * DIM);
        const float4* k3 = (const float4*)(kb + (size_t)id3 * DIM);
        float4 a0 = k0[sub], b0 = k0[sub + 8];
        float4 a1 = k1[sub], b1 = k1[sub + 8];
        float4 a2 = k2[sub], b2 = k2[sub + 8];
        float4 a3 = k3[sub], b3 = k3[sub + 8];
        float d0 = qa.x*a0.x + qa.y*a0.y + qa.z*a0.z + qa.w*a0.w
                 + qb.x*b0.x + qb.y*b0.y + qb.z*b0.z + qb.w*b0.w;
        float d1 = qa.x*a1.x + qa.y*a1.y + qa.z*a1.z + qa.w*a1.w
                 + qb.x*b1.x + qb.y*b1.y + qb.z*b1.z + qb.w*b1.w;
        float d2 = qa.x*a2.x + qa.y*a2.y + qa.z*a2.z + qa.w*a2.w
                 + qb.x*b2.x + qb.y*b2.y + qb.z*b2.z + qb.w*b2.w;
        float d3 = qa.x*a3.x + qa.y*a3.y + qa.z*a3.z + qa.w*a3.w
                 + qb.x*b3.x + qb.y*b3.y + qb.z*b3.z + qb.w*b3.w;
#pragma unroll
        for (int o = 4; o; o >>= 1) {
            d0 += __shfl_xor_sync(0xffffffffu, d0, o);
            d1 += __shfl_xor_sync(0xffffffffu, d1, o);
            d2 += __shfl_xor_sync(0xffffffffu, d2, o);
            d3 += __shfl_xor_sync(0xffffffffu, d3, o);
        }
        mx = fmaxf(fmaxf(fmaxf(mx, d0), fmaxf(d1, d2)), d3);
        sm += (d0 + d1) + (d2 + d3);
    }
    {   // s = 40
        int i = (int)ip[40];
        const float4* kr = (const float4*)(kb + (size_t)i * DIM);
        float4 ka = kr[sub], kc = kr[sub + 8];
        float d = qa.x*ka.x + qa.y*ka.y + qa.z*ka.z + qa.w*ka.w
                + qb.x*kc.x + qb.y*kc.y + qb.z*kc.z + qb.w*kc.w;
#pragma unroll
        for (int o = 4; o; o >>= 1) d += __shfl_xor_sync(0xffffffffu, d, o);
        mx = fmaxf(mx, d);
        sm += d;
    }
    if (sub == 0) g_m[qid] = mx - sm * (1.0f / (float)NS);
}

extern "C" __global__ void __launch_bounds__(256)
kA(const float* __restrict__ q, const float* __restrict__ k,
   const void* __restrict__ idxraw, int qid0) {
    int gwarp = (blockIdx.x * blockDim.x + threadIdx.x) >> 5;
    int lane  = threadIdx.x & 31;
    int grp   = lane >> 3;
    int sub   = lane & 7;
    int qid   = qid0 + gwarp * 4 + grp;
    if (qid >= BH * LSEQ) return;
    int bh = qid >> 12;
    int qq = qid & (LSEQ - 1);

    // dtype sniff: int32 data read as int64 packs two random indices -> >= 2^32
    const long long* i64 = (const long long*)idxraw;
    bool w64 = (i64[1] >= 0 && i64[1] < LSEQ) &&
               (i64[3] >= 0 && i64[3] < LSEQ) &&
               (i64[5] >= 0 && i64[5] < LSEQ);
    if (w64) kA_impl<long long>(q, k, (const long long*)idxraw, bh, qq, qid, sub);
    else     kA_impl<int>(q, k, (const int*)idxraw, bh, qq, qid, sub);
}

// ---------------- Kernel B: top-41 indices per (b,h) ----------------
__global__ void kB(int bh0) {
    __shared__ float sv[LSEQ];
    __shared__ float tv[256];
    __shared__ int   ti[256];
    __shared__ float rv[8];
    __shared__ int   ri[8];
    __shared__ int   s_owner;
    int bh = bh0 + blockIdx.x;
    int tid = threadIdx.x;
    for (int i = tid; i < LSEQ; i += 256) sv[i] = g_m[bh * LSEQ + i];
    if (tid == 0) s_owner = -1;
    __syncthreads();

    int lane = tid & 31, w = tid >> 5;
    for (int t = 0; t < NS; t++) {
        if (t == 0 || s_owner == tid) {
            float bv = -INFINITY; int bi = 0;
            for (int i = tid; i < LSEQ; i += 256) {
                float x = sv[i];
                if (x > bv) { bv = x; bi = i; }
            }
            tv[tid] = bv; ti[tid] = bi;
        }
        __syncthreads();
        float bv = tv[tid]; int bi = ti[tid];
#pragma unroll
        for (int o = 16; o; o >>= 1) {
            float ov = __shfl_xor_sync(0xffffffffu, bv, o);
            int   oi = __shfl_xor_sync(0xffffffffu, bi, o);
            if (ov > bv || (ov == bv && oi < bi)) { bv = ov; bi = oi; }
        }
        if (lane == 0) { rv[w] = bv; ri[w] = bi; }
        __syncthreads();
        if (tid == 0) {
            float b2 = rv[0]; int i2 = ri[0];
            for (int w2 = 1; w2 < 8; w2++)
                if (rv[w2] > b2 || (rv[w2] == b2 && ri[w2] < i2)) { b2 = rv[w2]; i2 = ri[w2]; }
            g_topq[bh * NS + t] = i2;
            sv[i2] = -INFINITY;
            s_owner = i2 & 255;
        }
        __syncthreads();
    }
}

// ---------------- Kernel C1a: partial v sums (512 blocks) ----------------
__global__ void kC1a(const float* __restrict__ v) {
    __shared__ float red[256];
    int blk = blockIdx.x;              // bh*16 + slice
    int bh = blk >> 4, sl = blk & 15;
    int tid = threadIdx.x;
    int d = tid & 63, g = tid >> 6;
    const float* vb = v + ((size_t)bh * LSEQ + sl * 256) * DIM;
    float acc = 0.f;
    for (int r = g; r < 256; r += 4) acc += vb[(size_t)r * DIM + d];
    red[tid] = acc;
    __syncthreads();
    if (tid < 64)
        g_vpart[blk * DIM + tid] =
            red[tid] + red[tid + 64] + red[tid + 128] + red[tid + 192];
}

// ---------------- Kernel C1b: reduce partials to mean ----------------
__global__ void kC1b() {
    int bh = blockIdx.x, d = threadIdx.x;
    float acc = 0.f;
#pragma unroll
    for (int s = 0; s < 16; s++) acc += g_vpart[(bh * 16 + s) * DIM + d];
    g_vmean[bh * DIM + d] = acc * (1.0f / (float)LSEQ);
}

// ---------------- Kernel C2: fill output with broadcast mean ----------------
__global__ void kC2(float* __restrict__ out) {
    size_t i = ((size_t)blockIdx.x * 256 + threadIdx.x) * 4;
    int bh = (int)(i >> 18);          // 4096*64 = 2^18
    int d  = (int)(i & 63);
    float4 val = *(const float4*)&g_vmean[bh * DIM + d];
    *(float4*)&out[i] = val;
}

// ---------------- Kernel D: split-K attention for the 41 selected queries ----
// grid = bh*NSPLIT, 256 threads, 2 blocks/SM. QK: 2 k-rows x 11 q-rows per
// thread. Softmax parallel across all 8 warps (fast __expf).
extern "C" __global__ void __launch_bounds__(256, 2)
kD(const float* __restrict__ q, const float* __restrict__ k, const float* __restrict__ v) {
    extern __shared__ float dynsm[];
    float* qs = dynsm;                       // QROWS*64 = 2816
    float* kt = qs + QROWS * 64;             // 128*68   = 8704
    float* sc = kt + KTILE * 68;             // QROWS*260= 11440

    int bh  = blockIdx.x >> 4;
    int sp  = blockIdx.x & (NSPLIT - 1);
    int tid = threadIdx.x;

    for (int i = tid; i < QROWS * 64; i += 256) {
        int qi = i >> 6, d = i & 63;
        float val = 0.f;
        if (qi < NS) {
            int row = g_topq[bh * NS + qi];
            val = q[((size_t)bh * LSEQ + row) * DIM + d] * 0.125f;
        }
        qs[i] = val;
    }
    __syncthreads();

    int j = tid & 63;                 // k rows j and j+64
    int h = tid >> 6;                 // q group: rows h*11 .. h*11+10
    const float* kc = k + ((size_t)bh * LSEQ + sp * CHUNK) * DIM;

    float acc0[11], acc1[11];
    for (int tile = 0; tile < CHUNK / KTILE; tile++) {
        __syncthreads();
        for (int i = tid; i < KTILE * 64; i += 256) {
            int r = i >> 6, c = i & 63;
            kt[r * 68 + c] = kc[(size_t)tile * KTILE * DIM + i];
        }
        __syncthreads();
#pragma unroll
        for (int a = 0; a < 11; a++) { acc0[a] = 0.f; acc1[a] = 0.f; }
#pragma unroll 4
        for (int t = 0; t < 64; t += 4) {
            float4 kv0 = *(const float4*)&kt[j * 68 + t];
            float4 kv1 = *(const float4*)&kt[(j + 64) * 68 + t];
#pragma unroll
            for (int a = 0; a < 11; a++) {
                float4 qv = *(const float4*)&qs[(h * 11 + a) * 64 + t];
                acc0[a] += kv0.x * qv.x + kv0.y * qv.y + kv0.z * qv.z + kv0.w * qv.w;
                acc1[a] += kv1.x * qv.x + kv1.y * qv.y + kv1.z * qv.z + kv1.w * qv.w;
            }
        }
#pragma unroll
        for (int a = 0; a < 11; a++) {
            sc[(h * 11 + a) * 260 + tile * KTILE + j]      = acc0[a];
            sc[(h * 11 + a) * 260 + tile * KTILE + j + 64] = acc1[a];
        }
    }
    __syncthreads();

    // parallel softmax: warp w handles rows w, w+8, ...; lane owns cols
    // lane*4..lane*4+3 and 128+lane*4.. (conflict-free LDS.128).
    {
        int lane = tid & 31, w = tid >> 5;
        for (int r = w; r < NS; r += 8) {
            float4* row4 = (float4*)&sc[r * 260];
            float4 x0 = row4[lane];
            float4 x1 = row4[32 + lane];
            float M = fmaxf(fmaxf(fmaxf(x0.x, x0.y), fmaxf(x0.z, x0.w)),
                            fmaxf(fmaxf(x1.x, x1.y), fmaxf(x1.z, x1.w)));
#pragma unroll
            for (int o = 16; o; o >>= 1)
                M = fmaxf(M, __shfl_xor_sync(0xffffffffu, M, o));
            x0.x = __expf(x0.x - M); x0.y = __expf(x0.y - M);
            x0.z = __expf(x0.z - M); x0.w = __expf(x0.w - M);
            x1.x = __expf(x1.x - M); x1.y = __expf(x1.y - M);
            x1.z = __expf(x1.z - M); x1.w = __expf(x1.w - M);
            row4[lane] = x0;
            row4[32 + lane] = x1;
            float Lx = (x0.x + x0.y) + (x0.z + x0.w)
                     + (x1.x + x1.y) + (x1.z + x1.w);
#pragma unroll
            for (int o = 16; o; o >>= 1)
                Lx += __shfl_xor_sync(0xffffffffu, Lx, o);
            if (lane == 0) {
                g_pm[(bh * NSPLIT + sp) * NS + r] = M;
                g_pl[(bh * NSPLIT + sp) * NS + r] = Lx;
            }
        }
    }
    __syncthreads();

    int dq = tid & 15;
    int qg = tid >> 4;
    const float4* vc4 = (const float4*)(v + ((size_t)bh * LSEQ + sp * CHUNK) * DIM);
    float4 o0 = {0.f, 0.f, 0.f, 0.f};
    float4 o1 = {0.f, 0.f, 0.f, 0.f};
    float4 o2 = {0.f, 0.f, 0.f, 0.f};
    bool has2 = (qg + 32) < NS;
    const float4* sc0 = (const float4*)&sc[qg * 260];
    const float4* sc1 = (const float4*)&sc[(qg + 16) * 260];
    const float4* sc2 = (const float4*)&sc[(has2 ? qg + 32 : qg) * 260];
#pragma unroll 4
    for (int u = 0; u < 64; u++) {
        float4 p0 = sc0[u];
        float4 p1 = sc1[u];
        float4 p2 = sc2[u];
        float4 v0 = vc4[(u * 4 + 0) * 16 + dq];
        float4 v1 = vc4[(u * 4 + 1) * 16 + dq];
        float4 v2 = vc4[(u * 4 + 2) * 16 + dq];
        float4 v3 = vc4[(u * 4 + 3) * 16 + dq];
        o0.x += p0.x*v0.x + p0.y*v1.x + p0.z*v2.x + p0.w*v3.x;
        o0.y += p0.x*v0.y + p0.y*v1.y + p0.z*v2.y + p0.w*v3.y;
        o0.z += p0.x*v0.z + p0.y*v1.z + p0.z*v2.z + p0.w*v3.z;
        o0.w += p0.x*v0.w + p0.y*v1.w + p0.z*v2.w + p0.w*v3.w;
        o1.x += p1.x*v0.x + p1.y*v1.x + p1.z*v2.x + p1.w*v3.x;
        o1.y += p1.x*v0.y + p1.y*v1.y + p1.z*v2.y + p1.w*v3.y;
        o1.z += p1.x*v0.z + p1.y*v1.z + p1.z*v2.z + p1.w*v3.z;
        o1.w += p1.x*v0.w + p1.y*v1.w + p1.z*v2.w + p1.w*v3.w;
        o2.x += p2.x*v0.x + p2.y*v1.x + p2.z*v2.x + p2.w*v3.x;
        o2.y += p2.x*v0.y + p2.y*v1.y + p2.z*v2.y + p2.w*v3.y;
        o2.z += p2.x*v0.z + p2.y*v1.z + p2.z*v2.z + p2.w*v3.z;
        o2.w += p2.x*v0.w + p2.y*v1.w + p2.z*v2.w + p2.w*v3.w;
    }
    float4* pb4 = (float4*)(g_pacc + (size_t)(bh * NSPLIT + sp) * NS * DIM);
    pb4[qg * 16 + dq]        = o0;
    pb4[(qg + 16) * 16 + dq] = o1;
    if (has2) pb4[(qg + 32) * 16 + dq] = o2;
}

// ---------------- Kernel E: combine splits, scatter selected rows ----------------
__global__ void kE(float* __restrict__ out) {
    int gw   = (blockIdx.x * blockDim.x + threadIdx.x) >> 5;
    int lane = threadIdx.x & 31;
    if (gw >= BH * NS) return;
    int bh = gw / NS, n = gw % NS;

    float M = -INFINITY;
#pragma unroll
    for (int s = 0; s < NSPLIT; s++) M = fmaxf(M, g_pm[(bh * NSPLIT + s) * NS + n]);
    float w[NSPLIT];
    float Lx = 0.f;
#pragma unroll
    for (int s = 0; s < NSPLIT; s++) {
        float ws = __expf(g_pm[(bh * NSPLIT + s) * NS + n] - M);
        w[s] = ws;
        Lx += g_pl[(bh * NSPLIT + s) * NS + n] * ws;
    }
    float o0 = 0.f, o1 = 0.f;
#pragma unroll
    for (int s = 0; s < NSPLIT; s++) {
        const float* pa = g_pacc + ((size_t)(bh * NSPLIT + s) * NS + n) * DIM;
        o0 += pa[lane] * w[s];
        o1 += pa[lane + 32] * w[s];
    }
    int row = g_topq[bh * NS + n];
    float inv = 1.0f / Lx;
    out[((size_t)bh * LSEQ + row) * DIM + lane]      = o0 * inv;
    out[((size_t)bh * LSEQ + row) * DIM + lane + 32] = o1 * inv;
}

// ---------------- launch ----------------
extern "C" void kernel_launch(void* const* d_in, const int* in_sizes, int n_in,
                              void* d_out, int out_size) {
    const float* q = (const float*)d_in[0];
    const float* k = (const float*)d_in[1];
    const float* v = (const float*)d_in[2];
    const void*  idx = (const void*)d_in[3];   // int32 or int64, auto-detected in kA
    float* out = (float*)d_out;

    // one-time stream/event setup (host-side objects only; no device memory)
    static bool inited = false;
    static cudaStream_t s2 = nullptr;
    static cudaEvent_t ev_fork = nullptr, ev_half = nullptr, ev_kb0 = nullptr, ev_join = nullptr;
    if (!inited) {
        inited = true;
        bool ok = (cudaStreamCreateWithFlags(&s2, cudaStreamNonBlocking) == cudaSuccess);
        ok = ok && (cudaEventCreateWithFlags(&ev_fork, cudaEventDisableTiming) == cudaSuccess);
        ok = ok && (cudaEventCreateWithFlags(&ev_half, cudaEventDisableTiming) == cudaSuccess);
        ok = ok && (cudaEventCreateWithFlags(&ev_kb0, cudaEventDisableTiming) == cudaSuccess);
        ok = ok && (cudaEventCreateWithFlags(&ev_join, cudaEventDisableTiming) == cudaSuccess);
        if (!ok) s2 = nullptr;
    }

    const int kD_smem = (QROWS * 64 + KTILE * 68 + QROWS * 260) * (int)sizeof(float);
    cudaFuncSetAttribute((const void*)kD, cudaFuncAttributeMaxDynamicSharedMemorySize, kD_smem);

    const int HALF_QIDS   = BHHALF * LSEQ;          // 65536
    const int HALF_BLOCKS = HALF_QIDS / 32;         // 2048

    if (s2) {
        // fork: v-mean chain on s2 (finishes well before the kB fork point)
        cudaEventRecord(ev_fork, 0);
        cudaStreamWaitEvent(s2, ev_fork, 0);
        kC1a<<<BH * 16, 256, 0, s2>>>(v);
        kC1b<<<BH, 64, 0, s2>>>();
        kC2<<<(BH * LSEQ * DIM) / (256 * 4), 256, 0, s2>>>(out);

        // kA half 1 (bh 0..15) then half 2; kB(0..15) on s2 overlaps half 2
        kA<<<HALF_BLOCKS, 256>>>(q, k, idx, 0);
        cudaEventRecord(ev_half, 0);
        kA<<<HALF_BLOCKS, 256>>>(q, k, idx, HALF_QIDS);

        cudaStreamWaitEvent(s2, ev_half, 0);
        kB<<<BHHALF, 256, 0, s2>>>(0);
        cudaEventRecord(ev_kb0, s2);

        // second kB half on stream 0 after kA half 2
        kB<<<BHHALF, 256>>>(BHHALF);

        // kD needs both kB halves
        cudaStreamWaitEvent(0, ev_kb0, 0);
        kD<<<BH * NSPLIT, 256, kD_smem>>>(q, k, v);

        // kE also needs kC2 (s2) — ev_kb0 already orders kC2 (same stream, earlier)
        kE<<<(BH * NS + 7) / 8, 256>>>(out);
    } else {
        // serial fallback
        kA<<<2 * HALF_BLOCKS, 256>>>(q, k, idx, 0);
        kB<<<BH, 256>>>(0);
        kC1a<<<BH * 16, 256>>>(v);
        kC1b<<<BH, 64>>>();
        kC2<<<(BH * LSEQ * DIM) / (256 * 4), 256>>>(out);
        kD<<<BH * NSPLIT, 256, kD_smem>>>(q, k, v);
        kE<<<(BH * NS + 7) / 8, 256>>>(out);
    }
}

// round 17
// speedup vs baseline: 1.1441x; 1.1441x over previous
#include <cuda_runtime.h>
#include <math.h>

#define BH     32
#define LSEQ   4096
#define DIM    64
#define NS     41        // sample_k == n_top == 41
#define NSPLIT 16
#define CHUNK  (LSEQ / NSPLIT)   // 256
#define KTILE  128
#define QROWS  44                // padded q rows in kD (rows >= 41 are zero)

// ---------------- device scratch (no allocations allowed) ----------------
__device__ float g_m[BH * LSEQ];                    // 512 KB
__device__ int   g_topq[BH * NS];
__device__ float g_vmean[BH * DIM];
__device__ float g_vpart[BH * 16 * DIM];
__device__ float g_pacc[BH * NSPLIT * NS * DIM];    // ~5.4 MB
__device__ float g_pm[BH * NSPLIT * NS];
__device__ float g_pl[BH * NSPLIT * NS];

// ---------------- Kernel A: m = max_s(q.k_s) - mean_s(q.k_s) ----------------
// kI fused: dtype of index_sample auto-detected in-kernel, body templated.
// 8 lanes per query; contiguous lane mapping: each warp-LDG covers full 128B
// lines (2 wavefronts per (query,key) pair = floor). Keys in chunks of 4 (MLP).
// 256-thread blocks, monolithic launch (frozen — measured structural floor).
template<typename IdxT>
__device__ __forceinline__ void kA_impl(const float* __restrict__ q,
                                        const float* __restrict__ k,
                                        const IdxT* __restrict__ idx,
                                        int bh, int qq, int qid, int sub) {
    const float4* qr = (const float4*)(q + ((size_t)bh * LSEQ + qq) * DIM);
    float4 qa = qr[sub];          // dims [4*sub, 4*sub+4)
    float4 qb = qr[sub + 8];      // dims [32+4*sub, 32+4*sub+4)
    const float* kb = k + (size_t)bh * LSEQ * DIM;
    const IdxT* ip = idx + (size_t)qq * NS;

    float mx = -INFINITY, sm = 0.f;
#pragma unroll
    for (int u = 0; u < 10; u++) {
        int id0 = (int)ip[u * 4 + 0];
        int id1 = (int)ip[u * 4 + 1];
        int id2 = (int)ip[u * 4 + 2];
        int id3 = (int)ip[u * 4 + 3];
        const float4* k0 = (const float4*)(kb + (size_t)id0 * DIM);
        const float4* k1 = (const float4*)(kb + (size_t)id1 * DIM);
        const float4* k2 = (const float4*)(kb + (size_t)id2 * DIM);
        const float4* k3 = (const float4*)(kb + (size_t)id3 * DIM);
        float4 a0 = k0[sub], b0 = k0[sub + 8];
        float4 a1 = k1[sub], b1 = k1[sub + 8];
        float4 a2 = k2[sub], b2 = k2[sub + 8];
        float4 a3 = k3[sub], b3 = k3[sub + 8];
        float d0 = qa.x*a0.x + qa.y*a0.y + qa.z*a0.z + qa.w*a0.w
                 + qb.x*b0.x + qb.y*b0.y + qb.z*b0.z + qb.w*b0.w;
        float d1 = qa.x*a1.x + qa.y*a1.y + qa.z*a1.z + qa.w*a1.w
                 + qb.x*b1.x + qb.y*b1.y + qb.z*b1.z + qb.w*b1.w;
        float d2 = qa.x*a2.x + qa.y*a2.y + qa.z*a2.z + qa.w*a2.w
                 + qb.x*b2.x + qb.y*b2.y + qb.z*b2.z + qb.w*b2.w;
        float d3 = qa.x*a3.x + qa.y*a3.y + qa.z*a3.z + qa.w*a3.w
                 + qb.x*b3.x + qb.y*b3.y + qb.z*b3.z + qb.w*b3.w;
#pragma unroll
        for (int o = 4; o; o >>= 1) {
            d0 += __shfl_xor_sync(0xffffffffu, d0, o);
            d1 += __shfl_xor_sync(0xffffffffu, d1, o);
            d2 += __shfl_xor_sync(0xffffffffu, d2, o);
            d3 += __shfl_xor_sync(0xffffffffu, d3, o);
        }
        mx = fmaxf(fmaxf(fmaxf(mx, d0), fmaxf(d1, d2)), d3);
        sm += (d0 + d1) + (d2 + d3);
    }
    {   // s = 40
        int i = (int)ip[40];
        const float4* kr = (const float4*)(kb + (size_t)i * DIM);
        float4 ka = kr[sub], kc = kr[sub + 8];
        float d = qa.x*ka.x + qa.y*ka.y + qa.z*ka.z + qa.w*ka.w
                + qb.x*kc.x + qb.y*kc.y + qb.z*kc.z + qb.w*kc.w;
#pragma unroll
        for (int o = 4; o; o >>= 1) d += __shfl_xor_sync(0xffffffffu, d, o);
        mx = fmaxf(mx, d);
        sm += d;
    }
    if (sub == 0) g_m[qid] = mx - sm * (1.0f / (float)NS);
}

extern "C" __global__ void __launch_bounds__(256)
kA(const float* __restrict__ q, const float* __restrict__ k,
   const void* __restrict__ idxraw) {
    int gwarp = (blockIdx.x * blockDim.x + threadIdx.x) >> 5;
    int lane  = threadIdx.x & 31;
    int grp   = lane >> 3;
    int sub   = lane & 7;
    int qid   = gwarp * 4 + grp;
    if (qid >= BH * LSEQ) return;
    int bh = qid >> 12;
    int qq = qid & (LSEQ - 1);

    // dtype sniff: int32 data read as int64 packs two random indices -> >= 2^32
    const long long* i64 = (const long long*)idxraw;
    bool w64 = (i64[1] >= 0 && i64[1] < LSEQ) &&
               (i64[3] >= 0 && i64[3] < LSEQ) &&
               (i64[5] >= 0 && i64[5] < LSEQ);
    if (w64) kA_impl<long long>(q, k, (const long long*)idxraw, bh, qq, qid, sub);
    else     kA_impl<int>(q, k, (const int*)idxraw, bh, qq, qid, sub);
}

// ---------------- Kernel B: top-41 indices per (b,h) ----------------
__global__ void kB() {
    __shared__ float sv[LSEQ];
    __shared__ float tv[256];
    __shared__ int   ti[256];
    __shared__ float rv[8];
    __shared__ int   ri[8];
    __shared__ int   s_owner;
    int bh = blockIdx.x;
    int tid = threadIdx.x;
    for (int i = tid; i < LSEQ; i += 256) sv[i] = g_m[bh * LSEQ + i];
    if (tid == 0) s_owner = -1;
    __syncthreads();

    int lane = tid & 31, w = tid >> 5;
    for (int t = 0; t < NS; t++) {
        if (t == 0 || s_owner == tid) {
            float bv = -INFINITY; int bi = 0;
            for (int i = tid; i < LSEQ; i += 256) {
                float x = sv[i];
                if (x > bv) { bv = x; bi = i; }
            }
            tv[tid] = bv; ti[tid] = bi;
        }
        __syncthreads();
        float bv = tv[tid]; int bi = ti[tid];
#pragma unroll
        for (int o = 16; o; o >>= 1) {
            float ov = __shfl_xor_sync(0xffffffffu, bv, o);
            int   oi = __shfl_xor_sync(0xffffffffu, bi, o);
            if (ov > bv || (ov == bv && oi < bi)) { bv = ov; bi = oi; }
        }
        if (lane == 0) { rv[w] = bv; ri[w] = bi; }
        __syncthreads();
        if (tid == 0) {
            float b2 = rv[0]; int i2 = ri[0];
            for (int w2 = 1; w2 < 8; w2++)
                if (rv[w2] > b2 || (rv[w2] == b2 && ri[w2] < i2)) { b2 = rv[w2]; i2 = ri[w2]; }
            g_topq[bh * NS + t] = i2;
            sv[i2] = -INFINITY;
            s_owner = i2 & 255;
        }
        __syncthreads();
    }
}

// ---------------- Kernel C1a: partial v sums (512 blocks) ----------------
__global__ void kC1a(const float* __restrict__ v) {
    __shared__ float red[256];
    int blk = blockIdx.x;              // bh*16 + slice
    int bh = blk >> 4, sl = blk & 15;
    int tid = threadIdx.x;
    int d = tid & 63, g = tid >> 6;
    const float* vb = v + ((size_t)bh * LSEQ + sl * 256) * DIM;
    float acc = 0.f;
    for (int r = g; r < 256; r += 4) acc += vb[(size_t)r * DIM + d];
    red[tid] = acc;
    __syncthreads();
    if (tid < 64)
        g_vpart[blk * DIM + tid] =
            red[tid] + red[tid + 64] + red[tid + 128] + red[tid + 192];
}

// ---------------- Kernel C1b: reduce partials to mean ----------------
__global__ void kC1b() {
    int bh = blockIdx.x, d = threadIdx.x;
    float acc = 0.f;
#pragma unroll
    for (int s = 0; s < 16; s++) acc += g_vpart[(bh * 16 + s) * DIM + d];
    g_vmean[bh * DIM + d] = acc * (1.0f / (float)LSEQ);
}

// ---------------- Kernel C2: fill output with broadcast mean ----------------
__global__ void kC2(float* __restrict__ out) {
    size_t i = ((size_t)blockIdx.x * 256 + threadIdx.x) * 4;
    int bh = (int)(i >> 18);          // 4096*64 = 2^18
    int d  = (int)(i & 63);
    float4 val = *(const float4*)&g_vmean[bh * DIM + d];
    *(float4*)&out[i] = val;
}

// ---------------- Kernel D: split-K attention for the 41 selected queries ----
// grid = bh*NSPLIT, 256 threads, 2 blocks/SM. QK: 2 k-rows x 11 q-rows per
// thread. Softmax parallel across all 8 warps (fast __expf).
extern "C" __global__ void __launch_bounds__(256, 2)
kD(const float* __restrict__ q, const float* __restrict__ k, const float* __restrict__ v) {
    extern __shared__ float dynsm[];
    float* qs = dynsm;                       // QROWS*64 = 2816
    float* kt = qs + QROWS * 64;             // 128*68   = 8704
    float* sc = kt + KTILE * 68;             // QROWS*260= 11440

    int bh  = blockIdx.x >> 4;
    int sp  = blockIdx.x & (NSPLIT - 1);
    int tid = threadIdx.x;

    for (int i = tid; i < QROWS * 64; i += 256) {
        int qi = i >> 6, d = i & 63;
        float val = 0.f;
        if (qi < NS) {
            int row = g_topq[bh * NS + qi];
            val = q[((size_t)bh * LSEQ + row) * DIM + d] * 0.125f;
        }
        qs[i] = val;
    }
    __syncthreads();

    int j = tid & 63;                 // k rows j and j+64
    int h = tid >> 6;                 // q group: rows h*11 .. h*11+10
    const float* kc = k + ((size_t)bh * LSEQ + sp * CHUNK) * DIM;

    float acc0[11], acc1[11];
    for (int tile = 0; tile < CHUNK / KTILE; tile++) {
        __syncthreads();
        for (int i = tid; i < KTILE * 64; i += 256) {
            int r = i >> 6, c = i & 63;
            kt[r * 68 + c] = kc[(size_t)tile * KTILE * DIM + i];
        }
        __syncthreads();
#pragma unroll
        for (int a = 0; a < 11; a++) { acc0[a] = 0.f; acc1[a] = 0.f; }
#pragma unroll 4
        for (int t = 0; t < 64; t += 4) {
            float4 kv0 = *(const float4*)&kt[j * 68 + t];
            float4 kv1 = *(const float4*)&kt[(j + 64) * 68 + t];
#pragma unroll
            for (int a = 0; a < 11; a++) {
                float4 qv = *(const float4*)&qs[(h * 11 + a) * 64 + t];
                acc0[a] += kv0.x * qv.x + kv0.y * qv.y + kv0.z * qv.z + kv0.w * qv.w;
                acc1[a] += kv1.x * qv.x + kv1.y * qv.y + kv1.z * qv.z + kv1.w * qv.w;
            }
        }
#pragma unroll
        for (int a = 0; a < 11; a++) {
            sc[(h * 11 + a) * 260 + tile * KTILE + j]      = acc0[a];
            sc[(h * 11 + a) * 260 + tile * KTILE + j + 64] = acc1[a];
        }
    }
    __syncthreads();

    // parallel softmax: warp w handles rows w, w+8, ...; lane owns cols
    // lane*4..lane*4+3 and 128+lane*4.. (conflict-free LDS.128).
    {
        int lane = tid & 31, w = tid >> 5;
        for (int r = w; r < NS; r += 8) {
            float4* row4 = (float4*)&sc[r * 260];
            float4 x0 = row4[lane];
            float4 x1 = row4[32 + lane];
            float M = fmaxf(fmaxf(fmaxf(x0.x, x0.y), fmaxf(x0.z, x0.w)),
                            fmaxf(fmaxf(x1.x, x1.y), fmaxf(x1.z, x1.w)));
#pragma unroll
            for (int o = 16; o; o >>= 1)
                M = fmaxf(M, __shfl_xor_sync(0xffffffffu, M, o));
            x0.x = __expf(x0.x - M); x0.y = __expf(x0.y - M);
            x0.z = __expf(x0.z - M); x0.w = __expf(x0.w - M);
            x1.x = __expf(x1.x - M); x1.y = __expf(x1.y - M);
            x1.z = __expf(x1.z - M); x1.w = __expf(x1.w - M);
            row4[lane] = x0;
            row4[32 + lane] = x1;
            float Lx = (x0.x + x0.y) + (x0.z + x0.w)
                     + (x1.x + x1.y) + (x1.z + x1.w);
#pragma unroll
            for (int o = 16; o; o >>= 1)
                Lx += __shfl_xor_sync(0xffffffffu, Lx, o);
            if (lane == 0) {
                g_pm[(bh * NSPLIT + sp) * NS + r] = M;
                g_pl[(bh * NSPLIT + sp) * NS + r] = Lx;
            }
        }
    }
    __syncthreads();

    int dq = tid & 15;
    int qg = tid >> 4;
    const float4* vc4 = (const float4*)(v + ((size_t)bh * LSEQ + sp * CHUNK) * DIM);
    float4 o0 = {0.f, 0.f, 0.f, 0.f};
    float4 o1 = {0.f, 0.f, 0.f, 0.f};
    float4 o2 = {0.f, 0.f, 0.f, 0.f};
    bool has2 = (qg + 32) < NS;
    const float4* sc0 = (const float4*)&sc[qg * 260];
    const float4* sc1 = (const float4*)&sc[(qg + 16) * 260];
    const float4* sc2 = (const float4*)&sc[(has2 ? qg + 32 : qg) * 260];
#pragma unroll 4
    for (int u = 0; u < 64; u++) {
        float4 p0 = sc0[u];
        float4 p1 = sc1[u];
        float4 p2 = sc2[u];
        float4 v0 = vc4[(u * 4 + 0) * 16 + dq];
        float4 v1 = vc4[(u * 4 + 1) * 16 + dq];
        float4 v2 = vc4[(u * 4 + 2) * 16 + dq];
        float4 v3 = vc4[(u * 4 + 3) * 16 + dq];
        o0.x += p0.x*v0.x + p0.y*v1.x + p0.z*v2.x + p0.w*v3.x;
        o0.y += p0.x*v0.y + p0.y*v1.y + p0.z*v2.y + p0.w*v3.y;
        o0.z += p0.x*v0.z + p0.y*v1.z + p0.z*v2.z + p0.w*v3.z;
        o0.w += p0.x*v0.w + p0.y*v1.w + p0.z*v2.w + p0.w*v3.w;
        o1.x += p1.x*v0.x + p1.y*v1.x + p1.z*v2.x + p1.w*v3.x;
        o1.y += p1.x*v0.y + p1.y*v1.y + p1.z*v2.y + p1.w*v3.y;
        o1.z += p1.x*v0.z + p1.y*v1.z + p1.z*v2.z + p1.w*v3.z;
        o1.w += p1.x*v0.w + p1.y*v1.w + p1.z*v2.w + p1.w*v3.w;
        o2.x += p2.x*v0.x + p2.y*v1.x + p2.z*v2.x + p2.w*v3.x;
        o2.y += p2.x*v0.y + p2.y*v1.y + p2.z*v2.y + p2.w*v3.y;
        o2.z += p2.x*v0.z + p2.y*v1.z + p2.z*v2.z + p2.w*v3.z;
        o2.w += p2.x*v0.w + p2.y*v1.w + p2.z*v2.w + p2.w*v3.w;
    }
    float4* pb4 = (float4*)(g_pacc + (size_t)(bh * NSPLIT + sp) * NS * DIM);
    pb4[qg * 16 + dq]        = o0;
    pb4[(qg + 16) * 16 + dq] = o1;
    if (has2) pb4[(qg + 32) * 16 + dq] = o2;
}

// ---------------- Kernel E: combine splits, scatter selected rows ----------------
__global__ void kE(float* __restrict__ out) {
    int gw   = (blockIdx.x * blockDim.x + threadIdx.x) >> 5;
    int lane = threadIdx.x & 31;
    if (gw >= BH * NS) return;
    int bh = gw / NS, n = gw % NS;

    float M = -INFINITY;
#pragma unroll
    for (int s = 0; s < NSPLIT; s++) M = fmaxf(M, g_pm[(bh * NSPLIT + s) * NS + n]);
    float w[NSPLIT];
    float Lx = 0.f;
#pragma unroll
    for (int s = 0; s < NSPLIT; s++) {
        float ws = __expf(g_pm[(bh * NSPLIT + s) * NS + n] - M);
        w[s] = ws;
        Lx += g_pl[(bh * NSPLIT + s) * NS + n] * ws;
    }
    float o0 = 0.f, o1 = 0.f;
#pragma unroll
    for (int s = 0; s < NSPLIT; s++) {
        const float* pa = g_pacc + ((size_t)(bh * NSPLIT + s) * NS + n) * DIM;
        o0 += pa[lane] * w[s];
        o1 += pa[lane + 32] * w[s];
    }
    int row = g_topq[bh * NS + n];
    float inv = 1.0f / Lx;
    out[((size_t)bh * LSEQ + row) * DIM + lane]      = o0 * inv;
    out[((size_t)bh * LSEQ + row) * DIM + lane + 32] = o1 * inv;
}

// ---------------- launch ----------------
extern "C" void kernel_launch(void* const* d_in, const int* in_sizes, int n_in,
                              void* d_out, int out_size) {
    const float* q = (const float*)d_in[0];
    const float* k = (const float*)d_in[1];
    const float* v = (const float*)d_in[2];
    const void*  idx = (const void*)d_in[3];   // int32 or int64, auto-detected in kA
    float* out = (float*)d_out;

    // one-time stream/event setup (host-side objects only; no device memory)
    static bool inited = false;
    static cudaStream_t s2 = nullptr;
    static cudaEvent_t ev_fork = nullptr, ev_join = nullptr;
    if (!inited) {
        inited = true;
        if (cudaStreamCreateWithFlags(&s2, cudaStreamNonBlocking) != cudaSuccess) s2 = nullptr;
        if (s2) {
            if (cudaEventCreateWithFlags(&ev_fork, cudaEventDisableTiming) != cudaSuccess ||
                cudaEventCreateWithFlags(&ev_join, cudaEventDisableTiming) != cudaSuccess) {
                s2 = nullptr;
            }
        }
    }

    const int kD_smem = (QROWS * 64 + KTILE * 68 + QROWS * 260) * (int)sizeof(float);
    cudaFuncSetAttribute((const void*)kD, cudaFuncAttributeMaxDynamicSharedMemorySize, kD_smem);

    if (s2) {
        // fork: v-mean chain on s2, overlapped with the kA path on stream 0
        cudaEventRecord(ev_fork, 0);
        cudaStreamWaitEvent(s2, ev_fork, 0);
        kC1a<<<BH * 16, 256, 0, s2>>>(v);
        kC1b<<<BH, 64, 0, s2>>>();
        kC2<<<(BH * LSEQ * DIM) / (256 * 4), 256, 0, s2>>>(out);
        cudaEventRecord(ev_join, s2);

        kA<<<4096, 256>>>(q, k, idx);
        kB<<<32, 256>>>();
        kD<<<BH * NSPLIT, 256, kD_smem>>>(q, k, v);

        // join: kE needs both kD (stream 0) and kC2 (s2)
        cudaStreamWaitEvent(0, ev_join, 0);
        kE<<<(BH * NS + 7) / 8, 256>>>(out);
    } else {
        // serial fallback
        kA<<<4096, 256>>>(q, k, idx);
        kB<<<32, 256>>>();
        kC1a<<<BH * 16, 256>>>(v);
        kC1b<<<BH, 64>>>();
        kC2<<<(BH * LSEQ * DIM) / (256 * 4), 256>>>(out);
        kD<<<BH * NSPLIT, 256, kD_smem>>>(q, k, v);
        kE<<<(BH * NS + 7) / 8, 256>>>(out);
    }
}